// round 15
// baseline (speedup 1.0000x reference)
#include <cuda_runtime.h>

// ---------------------------------------------------------------------------
// QWTForward: bicubic 2x downsample + 16 scaled copies.
//
//   D = downsample_bicubic(image)                 (4,16,256,256)
//   LL[b, g*16+c]        = D[b,c] * sLL[g]        (4,64,256,256)
//   H [b, g*16+c, band]  = D[b,c] * sH[band][g]   (4,64,3,256,256)
//
// R14: R10 barrier-free structure + __launch_bounds__(256, 6) to force
// regs <= ~40 and raise occupancy from 42% to ~62% (more warps issuing
// stores while others wait on their load batch).
// ---------------------------------------------------------------------------

#define B_    4
#define C_    16
#define HIN   512
#define WIN   512
#define HOUT  256
#define WOUT  256
#define PLANE (HOUT * WOUT)                // 65536
#define LL_TOTAL ((size_t)B_ * 64 * PLANE) // 16,777,216 floats

__global__ __launch_bounds__(256, 6)
void qwt_kernel(const float* __restrict__ image,
                const float* __restrict__ gl,
                const float* __restrict__ gh,
                const float* __restrict__ fl,
                const float* __restrict__ fh,
                float* __restrict__ out) {
    const int lane = threadIdx.x & 31;

    // Linear thread id -> (b, c, y, x4); x4 selects 4 consecutive output x.
    unsigned gtid = blockIdx.x * blockDim.x + threadIdx.x;
    int x4 = gtid & 63;          // 64 float4 per row; consecutive within warp
    int y  = (gtid >> 6) & 255;
    int c  = (gtid >> 14) & 15;
    int b  = gtid >> 18;

    const float w0 = -0.09375f, w1 = 0.59375f, w2 = 0.59375f, w3 = -0.09375f;
    const float wv[4] = {w0, w1, w2, w3};

    const float* __restrict__ plane = image + (size_t)(b * C_ + c) * (HIN * WIN);

    int ry[4];
    #pragma unroll
    for (int i = 0; i < 4; i++) {
        int r = 2 * y - 1 + i;
        ry[i] = min(max(r, 0), HIN - 1);
    }

    const int base = 8 * x4;
    const bool left_clamp  = (x4 == 0);
    const bool left_shfl   = (!left_clamp) && (lane > 0);
    const bool right_clamp = (x4 == 63);
    const bool right_shfl  = (!right_clamp) && (lane < 31);
    const bool left_load   = (!left_clamp) && (lane == 0);
    const bool right_load  = (!right_clamp) && (lane == 31);

    // ---- Issue ALL image loads first (8 independent LDG.128 + edge halos) ----
    float4 bv[4], cv[4];
    #pragma unroll
    for (int i = 0; i < 4; i++) {
        const float4* __restrict__ row4 =
            reinterpret_cast<const float4*>(plane + (size_t)ry[i] * WIN);
        bv[i] = __ldg(row4 + 2 * x4);       // cols base .. base+3
        cv[i] = __ldg(row4 + 2 * x4 + 1);   // cols base+4 .. base+7
    }
    float lm[4], rm[4];
    #pragma unroll
    for (int i = 0; i < 4; i++) {
        const float* __restrict__ row = plane + (size_t)ry[i] * WIN;
        lm[i] = left_load  ? __ldg(row + base - 1) : 0.f;
        rm[i] = right_load ? __ldg(row + base + 8) : 0.f;
    }

    // ---- Filter sums under the load shadow (lanes 0-3, serial index order;
    //      the sums cancel to ~1e-8 so association order is semantic) ----
    float fs = 0.f;
    if (lane < 4) {
        const float* __restrict__ f =
            (lane == 0) ? gl : (lane == 1) ? gh : (lane == 2) ? fl : fh;
        #pragma unroll
        for (int i = 0; i < 16; i++) fs += f[i];
    }
    const float vg = __shfl_sync(0xffffffffu, fs, 0);  // sum(gl)
    const float vh = __shfl_sync(0xffffffffu, fs, 1);  // sum(gh)
    const float vl = __shfl_sync(0xffffffffu, fs, 2);  // sum(fl)
    const float vf = __shfl_sync(0xffffffffu, fs, 3);  // sum(fh)

    // ---- Shuffle halos + horizontal/vertical convolution ----
    float d0 = 0.f, d1 = 0.f, d2 = 0.f, d3 = 0.f;
    #pragma unroll
    for (int i = 0; i < 4; i++) {
        float up = __shfl_up_sync(0xffffffffu, cv[i].w, 1);
        float dn = __shfl_down_sync(0xffffffffu, bv[i].x, 1);
        float vm1 = left_clamp  ? bv[i].x : (left_shfl  ? up : lm[i]);
        float vp8 = right_clamp ? cv[i].w : (right_shfl ? dn : rm[i]);

        float h0 = w0 * vm1      + w1 * bv[i].x + w2 * bv[i].y + w3 * bv[i].z;
        float h1 = w0 * bv[i].y  + w1 * bv[i].z + w2 * bv[i].w + w3 * cv[i].x;
        float h2 = w0 * bv[i].w  + w1 * cv[i].x + w2 * cv[i].y + w3 * cv[i].z;
        float h3 = w0 * cv[i].y  + w1 * cv[i].z + w2 * cv[i].w + w3 * vp8;

        float wi = wv[i];
        d0 = fmaf(wi, h0, d0);
        d1 = fmaf(wi, h1, d1);
        d2 = fmaf(wi, h2, d2);
        d3 = fmaf(wi, h3, d3);
    }

    size_t p = (size_t)y * WOUT + (size_t)x4 * 4;   // float4-aligned pixel offset

    // Scales inline: every sub-band scale is a product of two of {vg,vh,vl,vf};
    // g and band are unrolled constants so the selects are compile-time.
    #pragma unroll
    for (int g = 0; g < 4; g++) {
        size_t chan = (size_t)(b * 64 + g * 16 + c);
        const float pA = (g & 1)  ? vl : vg;   // lowpass family factor
        const float pB = (g >> 1) ? vl : vg;
        const float hA = (g & 1)  ? vf : vh;   // highpass family factor
        const float hB = (g >> 1) ? vf : vh;
        {
            float s = pA * pB;                                   // LL
            __stcs(reinterpret_cast<float4*>(out + chan * PLANE + p),
                   make_float4(d0 * s, d1 * s, d2 * s, d3 * s));
        }
        {
            float s = pA * hB;                                   // band 1
            __stcs(reinterpret_cast<float4*>(out + LL_TOTAL + (chan * 3 + 0) * PLANE + p),
                   make_float4(d0 * s, d1 * s, d2 * s, d3 * s));
        }
        {
            float s = hA * pB;                                   // band 2
            __stcs(reinterpret_cast<float4*>(out + LL_TOTAL + (chan * 3 + 1) * PLANE + p),
                   make_float4(d0 * s, d1 * s, d2 * s, d3 * s));
        }
        {
            float s = hA * hB;                                   // band 3
            __stcs(reinterpret_cast<float4*>(out + LL_TOTAL + (chan * 3 + 2) * PLANE + p),
                   make_float4(d0 * s, d1 * s, d2 * s, d3 * s));
        }
    }
}

extern "C" void kernel_launch(void* const* d_in, const int* in_sizes, int n_in,
                              void* d_out, int out_size) {
    const float* image = (const float*)d_in[0];
    const float* gl    = (const float*)d_in[1];
    const float* gh    = (const float*)d_in[2];
    const float* fl    = (const float*)d_in[3];
    const float* fh    = (const float*)d_in[4];
    float* out = (float*)d_out;

    // total threads = B*C*HOUT*(WOUT/4) = 4*16*256*64 = 1,048,576
    const int threads = 256;
    const int blocks = (B_ * C_ * HOUT * (WOUT / 4)) / threads;  // 4096
    qwt_kernel<<<blocks, threads>>>(image, gl, gh, fl, fh, out);
}

// round 16
// speedup vs baseline: 1.0287x; 1.0287x over previous
#include <cuda_runtime.h>

// ---------------------------------------------------------------------------
// QWTForward: bicubic 2x downsample + 16 scaled copies.
//
//   D = downsample_bicubic(image)                 (4,16,256,256)
//   LL[b, g*16+c]        = D[b,c] * sLL[g]        (4,64,256,256)
//   H [b, g*16+c, band]  = D[b,c] * sH[band][g]   (4,64,3,256,256)
//
// R15: R10 barrier-free structure (best), default write-back stores instead
// of __stcs (single-variable test: L2 writeback coalescing vs evict-first).
// ---------------------------------------------------------------------------

#define B_    4
#define C_    16
#define HIN   512
#define WIN   512
#define HOUT  256
#define WOUT  256
#define PLANE (HOUT * WOUT)                // 65536
#define LL_TOTAL ((size_t)B_ * 64 * PLANE) // 16,777,216 floats

__global__ __launch_bounds__(256)
void qwt_kernel(const float* __restrict__ image,
                const float* __restrict__ gl,
                const float* __restrict__ gh,
                const float* __restrict__ fl,
                const float* __restrict__ fh,
                float* __restrict__ out) {
    const int lane = threadIdx.x & 31;

    // Linear thread id -> (b, c, y, x4); x4 selects 4 consecutive output x.
    unsigned gtid = blockIdx.x * blockDim.x + threadIdx.x;
    int x4 = gtid & 63;          // 64 float4 per row; consecutive within warp
    int y  = (gtid >> 6) & 255;
    int c  = (gtid >> 14) & 15;
    int b  = gtid >> 18;

    const float w0 = -0.09375f, w1 = 0.59375f, w2 = 0.59375f, w3 = -0.09375f;
    const float wv[4] = {w0, w1, w2, w3};

    const float* __restrict__ plane = image + (size_t)(b * C_ + c) * (HIN * WIN);

    int ry[4];
    #pragma unroll
    for (int i = 0; i < 4; i++) {
        int r = 2 * y - 1 + i;
        ry[i] = min(max(r, 0), HIN - 1);
    }

    const int base = 8 * x4;
    const bool left_clamp  = (x4 == 0);
    const bool left_shfl   = (!left_clamp) && (lane > 0);
    const bool right_clamp = (x4 == 63);
    const bool right_shfl  = (!right_clamp) && (lane < 31);
    const bool left_load   = (!left_clamp) && (lane == 0);
    const bool right_load  = (!right_clamp) && (lane == 31);

    // ---- Issue ALL image loads first (8 independent LDG.128 + edge halos) ----
    float4 bv[4], cv[4];
    #pragma unroll
    for (int i = 0; i < 4; i++) {
        const float4* __restrict__ row4 =
            reinterpret_cast<const float4*>(plane + (size_t)ry[i] * WIN);
        bv[i] = __ldg(row4 + 2 * x4);       // cols base .. base+3
        cv[i] = __ldg(row4 + 2 * x4 + 1);   // cols base+4 .. base+7
    }
    float lm[4], rm[4];
    #pragma unroll
    for (int i = 0; i < 4; i++) {
        const float* __restrict__ row = plane + (size_t)ry[i] * WIN;
        lm[i] = left_load  ? __ldg(row + base - 1) : 0.f;
        rm[i] = right_load ? __ldg(row + base + 8) : 0.f;
    }

    // ---- Filter sums under the load shadow (lanes 0-3, serial index order;
    //      the sums cancel to ~1e-8 so association order is semantic) ----
    float fs = 0.f;
    if (lane < 4) {
        const float* __restrict__ f =
            (lane == 0) ? gl : (lane == 1) ? gh : (lane == 2) ? fl : fh;
        #pragma unroll
        for (int i = 0; i < 16; i++) fs += f[i];
    }
    const float vg = __shfl_sync(0xffffffffu, fs, 0);  // sum(gl)
    const float vh = __shfl_sync(0xffffffffu, fs, 1);  // sum(gh)
    const float vl = __shfl_sync(0xffffffffu, fs, 2);  // sum(fl)
    const float vf = __shfl_sync(0xffffffffu, fs, 3);  // sum(fh)

    // ---- Shuffle halos + horizontal/vertical convolution ----
    float d0 = 0.f, d1 = 0.f, d2 = 0.f, d3 = 0.f;
    #pragma unroll
    for (int i = 0; i < 4; i++) {
        float up = __shfl_up_sync(0xffffffffu, cv[i].w, 1);
        float dn = __shfl_down_sync(0xffffffffu, bv[i].x, 1);
        float vm1 = left_clamp  ? bv[i].x : (left_shfl  ? up : lm[i]);
        float vp8 = right_clamp ? cv[i].w : (right_shfl ? dn : rm[i]);

        float h0 = w0 * vm1      + w1 * bv[i].x + w2 * bv[i].y + w3 * bv[i].z;
        float h1 = w0 * bv[i].y  + w1 * bv[i].z + w2 * bv[i].w + w3 * cv[i].x;
        float h2 = w0 * bv[i].w  + w1 * cv[i].x + w2 * cv[i].y + w3 * cv[i].z;
        float h3 = w0 * cv[i].y  + w1 * cv[i].z + w2 * cv[i].w + w3 * vp8;

        float wi = wv[i];
        d0 = fmaf(wi, h0, d0);
        d1 = fmaf(wi, h1, d1);
        d2 = fmaf(wi, h2, d2);
        d3 = fmaf(wi, h3, d3);
    }

    size_t p = (size_t)y * WOUT + (size_t)x4 * 4;   // float4-aligned pixel offset

    // Scales inline: every sub-band scale is a product of two of {vg,vh,vl,vf};
    // g and band are unrolled constants so the selects are compile-time.
    // Default write-back stores (no .cs hint) — let L2 coalesce & drain lazily.
    #pragma unroll
    for (int g = 0; g < 4; g++) {
        size_t chan = (size_t)(b * 64 + g * 16 + c);
        const float pA = (g & 1)  ? vl : vg;   // lowpass family factor
        const float pB = (g >> 1) ? vl : vg;
        const float hA = (g & 1)  ? vf : vh;   // highpass family factor
        const float hB = (g >> 1) ? vf : vh;
        {
            float s = pA * pB;                                   // LL
            *reinterpret_cast<float4*>(out + chan * PLANE + p) =
                make_float4(d0 * s, d1 * s, d2 * s, d3 * s);
        }
        {
            float s = pA * hB;                                   // band 1
            *reinterpret_cast<float4*>(out + LL_TOTAL + (chan * 3 + 0) * PLANE + p) =
                make_float4(d0 * s, d1 * s, d2 * s, d3 * s);
        }
        {
            float s = hA * pB;                                   // band 2
            *reinterpret_cast<float4*>(out + LL_TOTAL + (chan * 3 + 1) * PLANE + p) =
                make_float4(d0 * s, d1 * s, d2 * s, d3 * s);
        }
        {
            float s = hA * hB;                                   // band 3
            *reinterpret_cast<float4*>(out + LL_TOTAL + (chan * 3 + 2) * PLANE + p) =
                make_float4(d0 * s, d1 * s, d2 * s, d3 * s);
        }
    }
}

extern "C" void kernel_launch(void* const* d_in, const int* in_sizes, int n_in,
                              void* d_out, int out_size) {
    const float* image = (const float*)d_in[0];
    const float* gl    = (const float*)d_in[1];
    const float* gh    = (const float*)d_in[2];
    const float* fl    = (const float*)d_in[3];
    const float* fh    = (const float*)d_in[4];
    float* out = (float*)d_out;

    // total threads = B*C*HOUT*(WOUT/4) = 4*16*256*64 = 1,048,576
    const int threads = 256;
    const int blocks = (B_ * C_ * HOUT * (WOUT / 4)) / threads;  // 4096
    qwt_kernel<<<blocks, threads>>>(image, gl, gh, fl, fh, out);
}

// round 17
// speedup vs baseline: 1.0311x; 1.0023x over previous
#include <cuda_runtime.h>

// ---------------------------------------------------------------------------
// QWTForward: bicubic 2x downsample + 16 scaled copies.
//
//   D = downsample_bicubic(image)                 (4,16,256,256)
//   LL[b, g*16+c]        = D[b,c] * sLL[g]        (4,64,256,256)
//   H [b, g*16+c, band]  = D[b,c] * sH[band][g]   (4,64,3,256,256)
//
// R16: 256-bit ld/st (sm_100+ .v8.f32). 8 output cols per thread; one warp
// spans a full output row, so horizontal halos are pure shfl/clamp (no
// scalar halo loads). 16 STG.256 per thread; 8 LDG.256 front-batched.
// ---------------------------------------------------------------------------

#define B_    4
#define C_    16
#define HIN   512
#define WIN   512
#define HOUT  256
#define WOUT  256
#define PLANE (HOUT * WOUT)                // 65536
#define LL_TOTAL ((size_t)B_ * 64 * PLANE) // 16,777,216 floats

__device__ __forceinline__ void ldg256(float* d, const float* p) {
    asm volatile("ld.global.nc.v8.f32 {%0,%1,%2,%3,%4,%5,%6,%7}, [%8];"
                 : "=f"(d[0]), "=f"(d[1]), "=f"(d[2]), "=f"(d[3]),
                   "=f"(d[4]), "=f"(d[5]), "=f"(d[6]), "=f"(d[7])
                 : "l"(p));
}

__device__ __forceinline__ void stg256(float* p, const float* d, float s) {
    asm volatile("st.global.v8.f32 [%0], {%1,%2,%3,%4,%5,%6,%7,%8};"
                 :: "l"(p),
                    "f"(d[0] * s), "f"(d[1] * s), "f"(d[2] * s), "f"(d[3] * s),
                    "f"(d[4] * s), "f"(d[5] * s), "f"(d[6] * s), "f"(d[7] * s)
                 : "memory");
}

__global__ __launch_bounds__(256)
void qwt_kernel(const float* __restrict__ image,
                const float* __restrict__ gl,
                const float* __restrict__ gh,
                const float* __restrict__ fl,
                const float* __restrict__ fh,
                float* __restrict__ out) {
    const int lane = threadIdx.x & 31;

    // Linear thread id -> (b, c, y, lane); lane covers 8 output cols.
    // One warp = one full output row (32 lanes x 8 cols = 256).
    unsigned gtid = blockIdx.x * blockDim.x + threadIdx.x;
    int y  = (gtid >> 5) & 255;
    int c  = (gtid >> 13) & 15;
    int b  = gtid >> 17;

    const float w0 = -0.09375f, w1 = 0.59375f, w2 = 0.59375f, w3 = -0.09375f;
    const float wv[4] = {w0, w1, w2, w3};

    const float* __restrict__ plane = image + (size_t)(b * C_ + c) * (HIN * WIN);

    int ry[4];
    #pragma unroll
    for (int i = 0; i < 4; i++) {
        int r = 2 * y - 1 + i;
        ry[i] = min(max(r, 0), HIN - 1);
    }

    const int base = 16 * lane;   // first input col of this thread's span

    // ---- Front-batch ALL input loads: 8 x LDG.256 (4 rows x 16 floats) ----
    float v[4][16];
    #pragma unroll
    for (int i = 0; i < 4; i++) {
        const float* __restrict__ row = plane + (size_t)ry[i] * WIN + base;
        ldg256(&v[i][0], row);
        ldg256(&v[i][8], row + 8);
    }

    // ---- Filter sums under the load shadow (lanes 0-3, serial index order;
    //      the sums cancel to ~1e-8 so association order is semantic) ----
    float fs = 0.f;
    if (lane < 4) {
        const float* __restrict__ f =
            (lane == 0) ? gl : (lane == 1) ? gh : (lane == 2) ? fl : fh;
        #pragma unroll
        for (int i = 0; i < 16; i++) fs += f[i];
    }
    const float vg = __shfl_sync(0xffffffffu, fs, 0);  // sum(gl)
    const float vh = __shfl_sync(0xffffffffu, fs, 1);  // sum(gh)
    const float vl = __shfl_sync(0xffffffffu, fs, 2);  // sum(fl)
    const float vf = __shfl_sync(0xffffffffu, fs, 3);  // sum(fh)

    // ---- Horizontal + vertical convolution ----
    // Output col 8*lane + j uses input cols base + 2j + {-1,0,1,2}.
    float d[8];
    #pragma unroll
    for (int j = 0; j < 8; j++) d[j] = 0.f;

    #pragma unroll
    for (int i = 0; i < 4; i++) {
        // Halos within the warp (warp spans the whole row; edges clamp).
        float up = __shfl_up_sync(0xffffffffu, v[i][15], 1);   // prev lane col base-1
        float dn = __shfl_down_sync(0xffffffffu, v[i][0], 1);  // next lane col base+16
        float vm1  = (lane == 0)  ? v[i][0]  : up;
        float vp16 = (lane == 31) ? v[i][15] : dn;

        float wi = wv[i];
        d[0] = fmaf(wi, w0 * vm1      + w1 * v[i][0]  + w2 * v[i][1]  + w3 * v[i][2],  d[0]);
        d[1] = fmaf(wi, w0 * v[i][1]  + w1 * v[i][2]  + w2 * v[i][3]  + w3 * v[i][4],  d[1]);
        d[2] = fmaf(wi, w0 * v[i][3]  + w1 * v[i][4]  + w2 * v[i][5]  + w3 * v[i][6],  d[2]);
        d[3] = fmaf(wi, w0 * v[i][5]  + w1 * v[i][6]  + w2 * v[i][7]  + w3 * v[i][8],  d[3]);
        d[4] = fmaf(wi, w0 * v[i][7]  + w1 * v[i][8]  + w2 * v[i][9]  + w3 * v[i][10], d[4]);
        d[5] = fmaf(wi, w0 * v[i][9]  + w1 * v[i][10] + w2 * v[i][11] + w3 * v[i][12], d[5]);
        d[6] = fmaf(wi, w0 * v[i][11] + w1 * v[i][12] + w2 * v[i][13] + w3 * v[i][14], d[6]);
        d[7] = fmaf(wi, w0 * v[i][13] + w1 * v[i][14] + w2 * v[i][15] + w3 * vp16,     d[7]);
    }

    size_t p = (size_t)y * WOUT + (size_t)lane * 8;   // 32B-aligned pixel offset

    // Scales inline: products of two of {vg,vh,vl,vf}; g/band compile-time.
    #pragma unroll
    for (int g = 0; g < 4; g++) {
        size_t chan = (size_t)(b * 64 + g * 16 + c);
        const float pA = (g & 1)  ? vl : vg;
        const float pB = (g >> 1) ? vl : vg;
        const float hA = (g & 1)  ? vf : vh;
        const float hB = (g >> 1) ? vf : vh;
        stg256(out + chan * PLANE + p,                          d, pA * pB); // LL
        stg256(out + LL_TOTAL + (chan * 3 + 0) * PLANE + p,     d, pA * hB); // band 1
        stg256(out + LL_TOTAL + (chan * 3 + 1) * PLANE + p,     d, hA * pB); // band 2
        stg256(out + LL_TOTAL + (chan * 3 + 2) * PLANE + p,     d, hA * hB); // band 3
    }
}

extern "C" void kernel_launch(void* const* d_in, const int* in_sizes, int n_in,
                              void* d_out, int out_size) {
    const float* image = (const float*)d_in[0];
    const float* gl    = (const float*)d_in[1];
    const float* gh    = (const float*)d_in[2];
    const float* fl    = (const float*)d_in[3];
    const float* fh    = (const float*)d_in[4];
    float* out = (float*)d_out;

    // total threads = B*C*HOUT*(WOUT/8) = 4*16*256*32 = 524,288
    const int threads = 256;
    const int blocks = (B_ * C_ * HOUT * (WOUT / 8)) / threads;  // 2048
    qwt_kernel<<<blocks, threads>>>(image, gl, gh, fl, fh, out);
}